// round 1
// baseline (speedup 1.0000x reference)
#include <cuda_runtime.h>
#include <cuda_bf16.h>
#include <math.h>

// GCN: out = log_softmax( spmm(adj, relu(spmm(adj, x@W1)+b1) @ W2) + b2 )
// spmm via on-the-fly CSR-by-dst build (int atomics only), gather-style
// segment sums (no float atomics). All scratch in __device__ globals.

#define MAXN 100000
#define MAXE 1600000

__device__ int   g_off[MAXN];          // counts -> starts -> ends
__device__ int   g_csr_src[MAXE];
__device__ float g_csr_val[MAXE];
__device__ float g_support1[(size_t)MAXN * 64];
__device__ float g_h[(size_t)MAXN * 64];
__device__ float g_support2[(size_t)MAXN * 16];

// ---------------------------------------------------------------- CSR build
__global__ void zero_off_kernel(int N) {
    int i = blockIdx.x * blockDim.x + threadIdx.x;
    if (i < N) g_off[i] = 0;
}

__global__ void hist_kernel(const int* __restrict__ dst, int E) {
    int i = blockIdx.x * blockDim.x + threadIdx.x;
    if (i < E) atomicAdd(&g_off[dst[i]], 1);
}

// Single-block exclusive scan over g_off[0..N): counts -> row starts.
__global__ void scan_kernel(int N) {
    __shared__ int warp_sums[32];
    int t = threadIdx.x;                      // 1024 threads
    int chunk = (N + 1023) >> 10;
    int begin = t * chunk;
    int end = min(begin + chunk, N);

    int local = 0;
    for (int i = begin; i < end; i++) local += g_off[i];

    int lane = t & 31, w = t >> 5;
    int v = local;
    #pragma unroll
    for (int d = 1; d < 32; d <<= 1) {
        int n = __shfl_up_sync(0xFFFFFFFFu, v, d);
        if (lane >= d) v += n;
    }
    if (lane == 31) warp_sums[w] = v;
    __syncthreads();                          // also fences phase-1 reads
    if (w == 0) {
        int s = warp_sums[lane];
        #pragma unroll
        for (int d = 1; d < 32; d <<= 1) {
            int n = __shfl_up_sync(0xFFFFFFFFu, s, d);
            if (lane >= d) s += n;
        }
        warp_sums[lane] = s;
    }
    __syncthreads();
    int excl = v - local + (w ? warp_sums[w - 1] : 0);

    int run = excl;
    for (int i = begin; i < end; i++) {       // rewrite own chunk only
        int c = g_off[i];
        g_off[i] = run;
        run += c;
    }
}

// Scatter edges; bumps g_off[dst] from start to end (row i = [off[i-1], off[i])).
__global__ void scatter_kernel(const int* __restrict__ src,
                               const int* __restrict__ dst,
                               const float* __restrict__ val, int E) {
    int i = blockIdx.x * blockDim.x + threadIdx.x;
    if (i < E) {
        int p = atomicAdd(&g_off[dst[i]], 1);
        g_csr_src[p] = src[i];
        g_csr_val[p] = val[i];
    }
}

// ---------------------------------------------------------------- GEMM1
// support1[N,64] = x[N,256] @ W1[256,64], tiled SGEMM BM=64 BN=64 BK=16,
// 256 threads, 4x4 microtile per thread.
__global__ void gemm1_kernel(const float* __restrict__ x,
                             const float* __restrict__ W1, int N) {
    __shared__ float As[16][68];   // [k][m], padded for aligned float4
    __shared__ float Bs[16][64];   // [k][n]

    int tid = threadIdx.x;
    int m0 = blockIdx.x * 64;
    int tm = (tid >> 4) << 2;      // 0..60
    int tn = (tid & 15) << 2;      // 0..60

    int ar = tid >> 2;             // 0..63 (tile row for A load)
    int ac = (tid & 3) << 2;       // 0,4,8,12
    int br = tid >> 4;             // 0..15 (k row for B load)
    int bc = (tid & 15) << 2;      // 0..60

    float acc[4][4] = {};

    for (int k0 = 0; k0 < 256; k0 += 16) {
        float4 av = make_float4(0.f, 0.f, 0.f, 0.f);
        int gr = m0 + ar;
        if (gr < N)
            av = *(const float4*)(x + (size_t)gr * 256 + k0 + ac);
        As[ac + 0][ar] = av.x;
        As[ac + 1][ar] = av.y;
        As[ac + 2][ar] = av.z;
        As[ac + 3][ar] = av.w;

        *(float4*)&Bs[br][bc] = *(const float4*)(W1 + (size_t)(k0 + br) * 64 + bc);
        __syncthreads();

        #pragma unroll
        for (int k = 0; k < 16; k++) {
            float a[4], b[4];
            *(float4*)a = *(const float4*)&As[k][tm];
            *(float4*)b = *(const float4*)&Bs[k][tn];
            #pragma unroll
            for (int i = 0; i < 4; i++)
                #pragma unroll
                for (int j = 0; j < 4; j++)
                    acc[i][j] = fmaf(a[i], b[j], acc[i][j]);
        }
        __syncthreads();
    }

    #pragma unroll
    for (int i = 0; i < 4; i++) {
        int gr = m0 + tm + i;
        if (gr < N)
            *(float4*)&g_support1[(size_t)gr * 64 + tn] =
                make_float4(acc[i][0], acc[i][1], acc[i][2], acc[i][3]);
    }
}

// ---------------------------------------------------------------- spMM1
// h[i,:] = relu( sum_{e in row i} w_e * support1[src_e,:] + b1 )
// 16 threads per node, one float4 of the 64 features each.
__global__ void spmm1_kernel(const float* __restrict__ b1, int N) {
    int t = blockIdx.x * blockDim.x + threadIdx.x;
    int node = t >> 4;
    if (node >= N) return;
    int c = (t & 15) << 2;

    int start = node ? g_off[node - 1] : 0;
    int end = g_off[node];

    float4 acc = make_float4(0.f, 0.f, 0.f, 0.f);
    for (int e = start; e < end; e++) {
        int s = g_csr_src[e];
        float w = g_csr_val[e];
        float4 v = *(const float4*)&g_support1[(size_t)s * 64 + c];
        acc.x = fmaf(w, v.x, acc.x);
        acc.y = fmaf(w, v.y, acc.y);
        acc.z = fmaf(w, v.z, acc.z);
        acc.w = fmaf(w, v.w, acc.w);
    }
    float4 bb = *(const float4*)&b1[c];
    acc.x = fmaxf(acc.x + bb.x, 0.f);
    acc.y = fmaxf(acc.y + bb.y, 0.f);
    acc.z = fmaxf(acc.z + bb.z, 0.f);
    acc.w = fmaxf(acc.w + bb.w, 0.f);
    *(float4*)&g_h[(size_t)node * 64 + c] = acc;
}

// ---------------------------------------------------------------- GEMM2
// support2[N,16] = h[N,64] @ W2[64,16]. 4 threads per node (k-split), quad
// shuffle reduce.
__global__ void gemm2_kernel(const float* __restrict__ W2, int N) {
    __shared__ float w2s[64 * 16];
    int tid = threadIdx.x;  // 256
    for (int i = tid; i < 64 * 16; i += 256) w2s[i] = W2[i];
    __syncthreads();

    int t = blockIdx.x * 256 + tid;
    int node = t >> 2;
    int part = t & 3;

    float acc[16] = {};
    if (node < N) {
        const float* hrow = &g_h[(size_t)node * 64 + part * 16];
        #pragma unroll
        for (int kk = 0; kk < 16; kk++) {
            float hv = hrow[kk];
            int k = part * 16 + kk;
            #pragma unroll
            for (int j = 0; j < 16; j++)
                acc[j] = fmaf(hv, w2s[k * 16 + j], acc[j]);
        }
    }
    #pragma unroll
    for (int j = 0; j < 16; j++) {
        acc[j] += __shfl_xor_sync(0xFFFFFFFFu, acc[j], 1);
        acc[j] += __shfl_xor_sync(0xFFFFFFFFu, acc[j], 2);
    }
    if (node < N && part == 0) {
        #pragma unroll
        for (int j = 0; j < 16; j += 4)
            *(float4*)&g_support2[(size_t)node * 16 + j] =
                make_float4(acc[j], acc[j + 1], acc[j + 2], acc[j + 3]);
    }
}

// ---------------------------------------------------------------- spMM2 + log_softmax
// 4 threads per node, one float4 of the 16 classes each; softmax stats via
// quad shuffles. No early return (shuffles need full warp convergence).
__global__ void spmm2_kernel(const float* __restrict__ b2,
                             float* __restrict__ out, int N) {
    int t = blockIdx.x * blockDim.x + threadIdx.x;
    int node = t >> 2;
    int q = (t & 3) << 2;

    float4 acc = make_float4(0.f, 0.f, 0.f, 0.f);
    if (node < N) {
        int start = node ? g_off[node - 1] : 0;
        int end = g_off[node];
        for (int e = start; e < end; e++) {
            int s = g_csr_src[e];
            float w = g_csr_val[e];
            float4 v = *(const float4*)&g_support2[(size_t)s * 16 + q];
            acc.x = fmaf(w, v.x, acc.x);
            acc.y = fmaf(w, v.y, acc.y);
            acc.z = fmaf(w, v.z, acc.z);
            acc.w = fmaf(w, v.w, acc.w);
        }
        float4 bb = *(const float4*)&b2[q];
        acc.x += bb.x; acc.y += bb.y; acc.z += bb.z; acc.w += bb.w;
    }

    float m = fmaxf(fmaxf(acc.x, acc.y), fmaxf(acc.z, acc.w));
    m = fmaxf(m, __shfl_xor_sync(0xFFFFFFFFu, m, 1));
    m = fmaxf(m, __shfl_xor_sync(0xFFFFFFFFu, m, 2));
    float s = expf(acc.x - m) + expf(acc.y - m) + expf(acc.z - m) + expf(acc.w - m);
    s += __shfl_xor_sync(0xFFFFFFFFu, s, 1);
    s += __shfl_xor_sync(0xFFFFFFFFu, s, 2);
    float lse = m + logf(s);

    if (node < N) {
        *(float4*)&out[(size_t)node * 16 + q] =
            make_float4(acc.x - lse, acc.y - lse, acc.z - lse, acc.w - lse);
    }
}

// ---------------------------------------------------------------- launch
extern "C" void kernel_launch(void* const* d_in, const int* in_sizes, int n_in,
                              void* d_out, int out_size) {
    const float* x    = (const float*)d_in[0];
    const int*   esrc = (const int*)d_in[1];
    const int*   edst = (const int*)d_in[2];
    const float* ev   = (const float*)d_in[3];
    const float* W1   = (const float*)d_in[4];
    const float* b1   = (const float*)d_in[5];
    const float* W2   = (const float*)d_in[6];
    const float* b2   = (const float*)d_in[7];
    float* out = (float*)d_out;

    int E = in_sizes[1];
    int N = in_sizes[0] / 256;

    // CSR build
    zero_off_kernel<<<(N + 255) / 256, 256>>>(N);
    hist_kernel<<<(E + 255) / 256, 256>>>(edst, E);
    scan_kernel<<<1, 1024>>>(N);
    scatter_kernel<<<(E + 255) / 256, 256>>>(esrc, edst, ev, E);

    // Layer 1
    gemm1_kernel<<<(N + 63) / 64, 256>>>(x, W1, N);
    spmm1_kernel<<<(N * 16 + 255) / 256, 256>>>(b1, N);

    // Layer 2 + log_softmax
    gemm2_kernel<<<(N * 4 + 255) / 256, 256>>>(W2, N);
    spmm2_kernel<<<(N * 4 + 255) / 256, 256>>>(b2, out, N);
}